// round 1
// baseline (speedup 1.0000x reference)
#include <cuda_runtime.h>
#include <cuda_bf16.h>
#include <math.h>

// Problem constants (fixed by the reference).
#define HS_B 8192
#define HS_P 32
#define HS_D 128

// Per-block partial loss sums (deterministic two-pass reduction, no atomics).
__device__ float g_hs_partial[HS_B];

// ---------------------------------------------------------------------------
// Main kernel: one CTA per batch row. 4 warps, each warp handles path
// positions p = warp, warp+4, ... and computes a full D=128 dot product via
// float4 lane loads + shuffle reduction. Positions >= target_path_len are
// skipped entirely (no gather traffic).
// ---------------------------------------------------------------------------
__global__ __launch_bounds__(128, 16)
void hs_main_kernel(const float* __restrict__ hidden,
                    const int*   __restrict__ target_path,
                    const int*   __restrict__ target_path_len,
                    const int*   __restrict__ target_code,
                    const float* __restrict__ embed_table) {
    const int b    = blockIdx.x;
    const int tid  = threadIdx.x;
    const int warp = tid >> 5;
    const int lane = tid & 31;

    __shared__ float4 sh_hidden[32];
    __shared__ float  sh_wsum[4];

    // Stage the hidden row (512 B) into shared once.
    if (tid < 32) {
        sh_hidden[tid] = reinterpret_cast<const float4*>(hidden + (size_t)b * HS_D)[tid];
    }
    __syncthreads();

    const float4 hv = sh_hidden[lane];
    const int    L  = target_path_len[b];

    float acc = 0.0f;

    #pragma unroll
    for (int p = warp; p < HS_P; p += 4) {
        if (p >= L) break;  // p is monotone per warp -> safe early exit

        const int node = target_path[b * HS_P + p];
        const float4 e =
            reinterpret_cast<const float4*>(embed_table + (size_t)node * HS_D)[lane];

        float d = e.x * hv.x + e.y * hv.y + e.z * hv.z + e.w * hv.w;

        // Warp-level reduction of the 128-dim dot product.
        #pragma unroll
        for (int off = 16; off > 0; off >>= 1)
            d += __shfl_xor_sync(0xffffffffu, d, off);

        if (lane == 0) {
            const float s    = 1.0f / (1.0f + expf(-d));
            const int   flag = target_code[b * HS_P + p];
            const float prob = flag ? s : (1.0f - s);
            acc += -logf(prob);
        }
    }

    if (lane == 0) sh_wsum[warp] = acc;
    __syncthreads();

    if (tid == 0)
        g_hs_partial[b] = sh_wsum[0] + sh_wsum[1] + sh_wsum[2] + sh_wsum[3];
}

// ---------------------------------------------------------------------------
// Finalize: single block reduces the 8192 partials in double precision and
// divides by the exact valid-position count (sum of path lengths).
// ---------------------------------------------------------------------------
__global__ void hs_finalize_kernel(const int* __restrict__ target_path_len,
                                   float* __restrict__ out) {
    __shared__ double    s_loss[256];
    __shared__ long long s_cnt[256];

    const int tid = threadIdx.x;
    double    ls  = 0.0;
    long long cnt = 0;

    for (int i = tid; i < HS_B; i += 256) {
        ls  += (double)g_hs_partial[i];
        cnt += (long long)target_path_len[i];
    }
    s_loss[tid] = ls;
    s_cnt[tid]  = cnt;
    __syncthreads();

    #pragma unroll
    for (int off = 128; off > 0; off >>= 1) {
        if (tid < off) {
            s_loss[tid] += s_loss[tid + off];
            s_cnt[tid]  += s_cnt[tid + off];
        }
        __syncthreads();
    }

    if (tid == 0) out[0] = (float)(s_loss[0] / (double)s_cnt[0]);
}

// ---------------------------------------------------------------------------
// Launch contract.
// Inputs (metadata order): hidden_ f32[B,D], target i32[B] (unused),
// target_path i32[B,P], target_path_len i32[B], target_code i32[B,P],
// embed_table f32[V,D].  Output: f32 scalar.
// ---------------------------------------------------------------------------
extern "C" void kernel_launch(void* const* d_in, const int* in_sizes, int n_in,
                              void* d_out, int out_size) {
    const float* hidden      = (const float*)d_in[0];
    const int*   target_path = (const int*)  d_in[2];
    const int*   path_len    = (const int*)  d_in[3];
    const int*   target_code = (const int*)  d_in[4];
    const float* embed_table = (const float*)d_in[5];
    float*       out         = (float*)d_out;

    hs_main_kernel<<<HS_B, 128>>>(hidden, target_path, path_len, target_code,
                                  embed_table);
    hs_finalize_kernel<<<1, 256>>>(path_len, out);
}

// round 2
// speedup vs baseline: 1.3253x; 1.3253x over previous
#include <cuda_runtime.h>
#include <cuda_bf16.h>
#include <math.h>

#define HS_B 8192
#define HS_P 32
#define HS_D 128

// Per-block {loss_sum, valid_count} partials (deterministic, no atomics).
__device__ float2 g_hs_partial[HS_B];

// ---------------------------------------------------------------------------
// Main kernel: one CTA per batch row, 256 threads = 8 warps.
// Warp w owns path positions p = w, w+8, w+16, w+24. All valid gathers are
// issued up front (MLP=4 per warp); the four 128-dim dot reductions share one
// interleaved 5-step shuffle butterfly.
// ---------------------------------------------------------------------------
__global__ __launch_bounds__(256, 8)
void hs_main_kernel(const float* __restrict__ hidden,
                    const int*   __restrict__ target_path,
                    const int*   __restrict__ target_path_len,
                    const int*   __restrict__ target_code,
                    const float* __restrict__ embed_table) {
    const int b    = blockIdx.x;
    const int tid  = threadIdx.x;
    const int warp = tid >> 5;
    const int lane = tid & 31;

    __shared__ float4 sh_hidden[32];
    __shared__ float  sh_wsum[8];

    if (tid < 32)
        sh_hidden[tid] = reinterpret_cast<const float4*>(hidden + (size_t)b * HS_D)[tid];
    __syncthreads();

    const float4 hv = sh_hidden[lane];
    const int    L  = target_path_len[b];

    int nodes[4];
    int flags[4];

    // Gather indices/flags up front (tiny, L2-resident).
    #pragma unroll
    for (int i = 0; i < 4; i++) {
        const int p = warp + i * 8;
        const bool valid = (p < L);
        nodes[i] = valid ? target_path[b * HS_P + p] : -1;
        flags[i] = valid ? target_code[b * HS_P + p] : 0;
    }

    // Issue all embed-row gathers back-to-back (predicated: no wasted traffic).
    float d[4];
    #pragma unroll
    for (int i = 0; i < 4; i++) {
        if (nodes[i] >= 0) {
            const float4 e =
                reinterpret_cast<const float4*>(embed_table + (size_t)nodes[i] * HS_D)[lane];
            d[i] = e.x * hv.x + e.y * hv.y + e.z * hv.z + e.w * hv.w;
        } else {
            d[i] = 0.0f;
        }
    }

    // Interleaved butterfly: 4 independent reductions share each step.
    #pragma unroll
    for (int off = 16; off > 0; off >>= 1) {
        #pragma unroll
        for (int i = 0; i < 4; i++)
            d[i] += __shfl_xor_sync(0xffffffffu, d[i], off);
    }

    if (lane == 0) {
        float acc = 0.0f;
        #pragma unroll
        for (int i = 0; i < 4; i++) {
            if (nodes[i] >= 0) {
                const float s    = 1.0f / (1.0f + __expf(-d[i]));
                const float prob = flags[i] ? s : (1.0f - s);
                acc += -__logf(prob);
            }
        }
        sh_wsum[warp] = acc;
    }
    __syncthreads();

    if (tid == 0) {
        float t = 0.0f;
        #pragma unroll
        for (int i = 0; i < 8; i++) t += sh_wsum[i];
        g_hs_partial[b] = make_float2(t, (float)L);
    }
}

// ---------------------------------------------------------------------------
// Finalize: one block, 1024 threads, 8 fully-unrolled independent loads per
// thread (MLP=8 over a 64 KB L2-resident array), then shuffle-tree reduce.
// Counts are integer-valued floats (< 2^24) so the count sum is exact.
// ---------------------------------------------------------------------------
__global__ __launch_bounds__(1024, 1)
void hs_finalize_kernel(float* __restrict__ out) {
    const int tid  = threadIdx.x;
    const int warp = tid >> 5;
    const int lane = tid & 31;

    float ls = 0.0f, cs = 0.0f;
    #pragma unroll
    for (int i = 0; i < 8; i++) {
        const float2 v = g_hs_partial[tid + i * 1024];
        ls += v.x;
        cs += v.y;
    }

    #pragma unroll
    for (int off = 16; off > 0; off >>= 1) {
        ls += __shfl_xor_sync(0xffffffffu, ls, off);
        cs += __shfl_xor_sync(0xffffffffu, cs, off);
    }

    __shared__ float s_loss[32];
    __shared__ float s_cnt[32];
    if (lane == 0) { s_loss[warp] = ls; s_cnt[warp] = cs; }
    __syncthreads();

    if (warp == 0) {
        ls = s_loss[lane];
        cs = s_cnt[lane];
        #pragma unroll
        for (int off = 16; off > 0; off >>= 1) {
            ls += __shfl_xor_sync(0xffffffffu, ls, off);
            cs += __shfl_xor_sync(0xffffffffu, cs, off);
        }
        if (lane == 0) out[0] = (float)((double)ls / (double)cs);
    }
}

// ---------------------------------------------------------------------------
// Inputs (metadata order): hidden_ f32[B,D], target i32[B] (unused),
// target_path i32[B,P], target_path_len i32[B], target_code i32[B,P],
// embed_table f32[V,D].  Output: f32 scalar.
// ---------------------------------------------------------------------------
extern "C" void kernel_launch(void* const* d_in, const int* in_sizes, int n_in,
                              void* d_out, int out_size) {
    const float* hidden      = (const float*)d_in[0];
    const int*   target_path = (const int*)  d_in[2];
    const int*   path_len    = (const int*)  d_in[3];
    const int*   target_code = (const int*)  d_in[4];
    const float* embed_table = (const float*)d_in[5];
    float*       out         = (float*)d_out;

    hs_main_kernel<<<HS_B, 256>>>(hidden, target_path, path_len, target_code,
                                  embed_table);
    hs_finalize_kernel<<<1, 1024>>>(out);
}

// round 4
// speedup vs baseline: 1.3293x; 1.0030x over previous
#include <cuda_runtime.h>
#include <cuda_bf16.h>
#include <math.h>

#define HS_B     8192
#define HS_P     32
#define HS_D     128
#define HS_GRID  1024
#define FULLMASK 0xffffffffu

// Per-CTA {loss_sum, count} partials + completion counter (zero-init).
__device__ float2       g_hs_partial[HS_GRID];
__device__ unsigned int g_hs_ctr;

// ---------------------------------------------------------------------------
// Fused kernel: 1024 CTAs x 256 threads. Warp w of CTA c owns batch row
// b = c*8 + w. One coalesced load grabs the row's 32 path indices + codes;
// dot products run in chunks of 8 concurrent row-gathers. The last CTA to
// finish reduces the 1024 partials and writes the scalar (fixed order =>
// deterministic), then resets the counter for graph replay.
// ---------------------------------------------------------------------------
__global__ __launch_bounds__(256)
void hs_fused_kernel(const float* __restrict__ hidden,
                     const int*   __restrict__ target_path,
                     const int*   __restrict__ target_path_len,
                     const int*   __restrict__ target_code,
                     const float* __restrict__ embed_table,
                     float*       __restrict__ out) {
    const int tid  = threadIdx.x;
    const int warp = tid >> 5;
    const int lane = tid & 31;
    const int b    = blockIdx.x * 8 + warp;

    // Hidden row: one float4 per lane (512 B coalesced).
    const float4 hv =
        reinterpret_cast<const float4*>(hidden + (size_t)b * HS_D)[lane];

    // All 32 path indices / codes for this row in one coalesced load each.
    const int node_l = target_path[b * HS_P + lane];
    const int code_l = target_code[b * HS_P + lane];
    const unsigned codemask = __ballot_sync(FULLMASK, code_l != 0);
    const int L = target_path_len[b];

    float acc = 0.0f;

    for (int c = 0; c * 8 < L; ++c) {
        float d[8];
        // 8 embed-row gathers in flight (each: 32 lanes x float4 = 512 B).
        #pragma unroll
        for (int i = 0; i < 8; i++) {
            const int p = c * 8 + i;
            const int node = __shfl_sync(FULLMASK, node_l, p & 31);
            d[i] = 0.0f;
            if (p < L) {
                const float4 e = reinterpret_cast<const float4*>(
                    embed_table + (size_t)node * HS_D)[lane];
                d[i] = e.x * hv.x + e.y * hv.y + e.z * hv.z + e.w * hv.w;
            }
        }
        // 8 interleaved butterfly reductions.
        #pragma unroll
        for (int off = 16; off > 0; off >>= 1) {
            #pragma unroll
            for (int i = 0; i < 8; i++)
                d[i] += __shfl_xor_sync(FULLMASK, d[i], off);
        }
        if (lane == 0) {
            #pragma unroll
            for (int i = 0; i < 8; i++) {
                const int p = c * 8 + i;
                if (p < L) {
                    const float x = ((codemask >> p) & 1u) ? d[i] : -d[i];
                    acc += __logf(1.0f + __expf(-x));  // -log(sigmoid(x))
                }
            }
        }
    }

    // Block-level partial.
    __shared__ float2 swsum[8];
    if (lane == 0) swsum[warp] = make_float2(acc, (float)L);
    __syncthreads();

    __shared__ bool is_last;
    if (tid == 0) {
        float2 t = make_float2(0.0f, 0.0f);
        #pragma unroll
        for (int i = 0; i < 8; i++) { t.x += swsum[i].x; t.y += swsum[i].y; }
        g_hs_partial[blockIdx.x] = t;
        __threadfence();
        const unsigned prev = atomicAdd(&g_hs_ctr, 1u);
        is_last = (prev == (unsigned)(gridDim.x - 1));
    }
    __syncthreads();

    // Last CTA reduces all 1024 partials (8 KB, L2) in fixed order.
    if (is_last) {
        float ls = 0.0f, cs = 0.0f;
        #pragma unroll
        for (int i = 0; i < 4; i++) {
            const float2 v = __ldcg(&g_hs_partial[tid + i * 256]);
            ls += v.x;
            cs += v.y;
        }
        #pragma unroll
        for (int off = 16; off > 0; off >>= 1) {
            ls += __shfl_xor_sync(FULLMASK, ls, off);
            cs += __shfl_xor_sync(FULLMASK, cs, off);
        }
        __shared__ float sl[8], sc[8];
        if (lane == 0) { sl[warp] = ls; sc[warp] = cs; }
        __syncthreads();
        if (tid == 0) {
            float tl = 0.0f, tc = 0.0f;
            #pragma unroll
            for (int i = 0; i < 8; i++) { tl += sl[i]; tc += sc[i]; }
            out[0] = (float)((double)tl / (double)tc);
            g_hs_ctr = 0;  // reset for next graph replay
        }
    }
}

// ---------------------------------------------------------------------------
// Inputs (metadata order): hidden_ f32[B,D], target i32[B] (unused),
// target_path i32[B,P], target_path_len i32[B], target_code i32[B,P],
// embed_table f32[V,D].  Output: f32 scalar.
// ---------------------------------------------------------------------------
extern "C" void kernel_launch(void* const* d_in, const int* in_sizes, int n_in,
                              void* d_out, int out_size) {
    const float* hidden      = (const float*)d_in[0];
    const int*   target_path = (const int*)  d_in[2];
    const int*   path_len    = (const int*)  d_in[3];
    const int*   target_code = (const int*)  d_in[4];
    const float* embed_table = (const float*)d_in[5];
    float*       out         = (float*)d_out;

    hs_fused_kernel<<<HS_GRID, 256>>>(hidden, target_path, path_len,
                                      target_code, embed_table, out);
}

// round 6
// speedup vs baseline: 1.4691x; 1.1052x over previous
#include <cuda_runtime.h>
#include <cuda_bf16.h>
#include <math.h>

#define HS_B     8192
#define HS_P     32
#define HS_D     128
#define HS_GRID  592                // 148 SMs x 4 CTAs, one wave
#define HS_ITEMS (HS_B * 4)         // (row, 8-pos chunk) work items
#define FULLMASK 0xffffffffu

// Per-CTA {loss_sum, count} partials + completion counter (zero-init).
__device__ float2       g_hs_partial[HS_GRID];
__device__ unsigned int g_hs_ctr;

// ---------------------------------------------------------------------------
// Balanced persistent kernel: each warp grid-strides over flat work items.
// Item = (b, c): positions [8c, 8c+8) of row b. All 8 row-gathers per item
// are independent and issued back-to-back; no cross-warp coupling until the
// final block/grid reduction. Skipped (fully-masked) items cost one int load.
// ---------------------------------------------------------------------------
__global__ __launch_bounds__(256)
void hs_fused_kernel(const float* __restrict__ hidden,
                     const int*   __restrict__ target_path,
                     const int*   __restrict__ target_path_len,
                     const int*   __restrict__ target_code,
                     const float* __restrict__ embed_table,
                     float*       __restrict__ out) {
    const int tid  = threadIdx.x;
    const int warp = tid >> 5;
    const int lane = tid & 31;
    const int gw   = blockIdx.x * 8 + warp;
    const int GW   = gridDim.x * 8;

    float accL = 0.0f;   // loss sum (valid on lane 0)
    float accC = 0.0f;   // valid-position count (valid on lane 0)

    for (int item = gw; item < HS_ITEMS; item += GW) {
        const int b    = item >> 2;
        const int base = (item & 3) * 8;
        const int L    = __ldg(&target_path_len[b]);
        if (base >= L) continue;                 // warp-uniform skip
        const int n = min(8, L - base);

        // Lanes 0..n-1 fetch this chunk's indices and codes (one 32B load each).
        int idx_l = 0, code_l = 0;
        const bool act = (lane < n);
        if (act) {
            idx_l  = target_path[b * HS_P + base + lane];
            code_l = target_code[b * HS_P + base + lane];
        }
        const unsigned codemask = __ballot_sync(FULLMASK, act && (code_l != 0));

        // Hidden row: one float4 per lane (512 B coalesced, L2-resident).
        const float4 hv =
            reinterpret_cast<const float4*>(hidden + (size_t)b * HS_D)[lane];

        // Up to 8 independent embed-row gathers in flight.
        float d[8];
        #pragma unroll
        for (int i = 0; i < 8; i++) {
            const int node = __shfl_sync(FULLMASK, idx_l, i);
            d[i] = 0.0f;
            if (i < n) {
                const float4 e = reinterpret_cast<const float4*>(
                    embed_table + (size_t)node * HS_D)[lane];
                d[i] = fmaf(e.x, hv.x, fmaf(e.y, hv.y,
                            fmaf(e.z, hv.z, e.w * hv.w)));
            }
        }

        // 8 interleaved butterfly reductions (5 steps).
        #pragma unroll
        for (int off = 16; off > 0; off >>= 1) {
            #pragma unroll
            for (int i = 0; i < 8; i++)
                d[i] += __shfl_xor_sync(FULLMASK, d[i], off);
        }

        if (lane == 0) {
            float s = 0.0f;
            #pragma unroll
            for (int i = 0; i < 8; i++) {
                if (i < n) {
                    const float x = ((codemask >> i) & 1u) ? d[i] : -d[i];
                    s += __logf(1.0f + __expf(-x));   // -log(sigmoid(x))
                }
            }
            accL += s;
            accC += (float)n;
        }
    }

    // Block-level partial (fixed order => deterministic).
    __shared__ float2 swsum[8];
    if (lane == 0) swsum[warp] = make_float2(accL, accC);
    __syncthreads();

    __shared__ bool is_last;
    if (tid == 0) {
        float2 t = make_float2(0.0f, 0.0f);
        #pragma unroll
        for (int i = 0; i < 8; i++) { t.x += swsum[i].x; t.y += swsum[i].y; }
        g_hs_partial[blockIdx.x] = t;
        __threadfence();
        const unsigned prev = atomicAdd(&g_hs_ctr, 1u);
        is_last = (prev == (unsigned)(gridDim.x - 1));
    }
    __syncthreads();

    // Last CTA reduces the 592 partials in fixed order and writes the scalar.
    if (is_last) {
        float ls = 0.0f, cs = 0.0f;
        #pragma unroll
        for (int i = 0; i < 3; i++) {
            const int j = tid + i * 256;
            if (j < HS_GRID) {
                const float2 v = __ldcg(&g_hs_partial[j]);
                ls += v.x;
                cs += v.y;
            }
        }
        #pragma unroll
        for (int off = 16; off > 0; off >>= 1) {
            ls += __shfl_xor_sync(FULLMASK, ls, off);
            cs += __shfl_xor_sync(FULLMASK, cs, off);
        }
        __shared__ float sl[8], sc[8];
        if (lane == 0) { sl[warp] = ls; sc[warp] = cs; }
        __syncthreads();
        if (tid == 0) {
            float tl = 0.0f, tc = 0.0f;
            #pragma unroll
            for (int i = 0; i < 8; i++) { tl += sl[i]; tc += sc[i]; }
            out[0] = (float)((double)tl / (double)tc);
            g_hs_ctr = 0;   // reset for next graph replay
        }
    }
}

// ---------------------------------------------------------------------------
// Inputs (metadata order): hidden_ f32[B,D], target i32[B] (unused),
// target_path i32[B,P], target_path_len i32[B], target_code i32[B,P],
// embed_table f32[V,D].  Output: f32 scalar.
// ---------------------------------------------------------------------------
extern "C" void kernel_launch(void* const* d_in, const int* in_sizes, int n_in,
                              void* d_out, int out_size) {
    const float* hidden      = (const float*)d_in[0];
    const int*   target_path = (const int*)  d_in[2];
    const int*   path_len    = (const int*)  d_in[3];
    const int*   target_code = (const int*)  d_in[4];
    const float* embed_table = (const float*)d_in[5];
    float*       out         = (float*)d_out;

    hs_fused_kernel<<<HS_GRID, 256>>>(hidden, target_path, path_len,
                                      target_code, embed_table, out);
}

// round 7
// speedup vs baseline: 2.2000x; 1.4975x over previous
#include <cuda_runtime.h>
#include <cuda_bf16.h>
#include <math.h>

#define HS_B     8192
#define HS_P     32
#define HS_D     128
#define HS_GRID  888                // 148 SMs x 6 CTAs (39 regs => 6/SM cap)
#define HS_ITEMS (HS_B * 4)         // (row, 8-pos chunk) work items
#define FULLMASK 0xffffffffu

// Per-CTA {loss_sum, count} partials + completion counter (zero-init).
__device__ float2       g_hs_partial[HS_GRID];
__device__ unsigned int g_hs_ctr;

// ---------------------------------------------------------------------------
// Balanced persistent kernel. Item = (b, c): positions [8c, 8c+8) of row b.
// 8 independent row-gathers per item; the 8 dot products are reduced by a
// folding merge network (9 SHFL instead of 40): after it, lane group
// k = lane>>2 holds the full dot for position j=k, so the softplus runs on
// 8 lanes in parallel and the loss accumulates in per-lane registers.
// ---------------------------------------------------------------------------
__global__ __launch_bounds__(256)
void hs_fused_kernel(const float* __restrict__ hidden,
                     const int*   __restrict__ target_path,
                     const int*   __restrict__ target_path_len,
                     const int*   __restrict__ target_code,
                     const float* __restrict__ embed_table,
                     float*       __restrict__ out) {
    const int tid  = threadIdx.x;
    const int warp = tid >> 5;
    const int lane = tid & 31;
    const int gw   = blockIdx.x * 8 + warp;
    const int GW   = gridDim.x * 8;

    const int  j     = lane >> 2;           // value index this lane finalizes
    const bool canon = (lane & 3) == 0;     // one canonical lane per value

    float accL = 0.0f;                      // per-lane loss accumulator
    float accC = 0.0f;                      // count accumulator (lane 0)

    for (int item = gw; item < HS_ITEMS; item += GW) {
        const int b    = item >> 2;
        const int base = (item & 3) * 8;
        const int L    = __ldg(&target_path_len[b]);
        if (base >= L) continue;            // warp-uniform skip
        const int n = min(8, L - base);

        // Lanes 0..n-1 fetch this chunk's indices and codes.
        int idx_l = 0, code_l = 0;
        const bool act = (lane < n);
        if (act) {
            idx_l  = target_path[b * HS_P + base + lane];
            code_l = target_code[b * HS_P + base + lane];
        }
        const unsigned codemask = __ballot_sync(FULLMASK, act && (code_l != 0));

        // Hidden row: one float4 per lane (512 B, L2-resident).
        const float4 hv =
            reinterpret_cast<const float4*>(hidden + (size_t)b * HS_D)[lane];

        // Up to 8 independent embed-row gathers in flight.
        float d[8];
        #pragma unroll
        for (int i = 0; i < 8; i++) {
            const int node = __shfl_sync(FULLMASK, idx_l, i);
            d[i] = 0.0f;
            if (i < n) {
                const float4 e = reinterpret_cast<const float4*>(
                    embed_table + (size_t)node * HS_D)[lane];
                d[i] = fmaf(e.x, hv.x, fmaf(e.y, hv.y,
                            fmaf(e.z, hv.z, e.w * hv.w)));
            }
        }

        // Folding merge network: 8 values -> 1 per lane group.
        // Step A (offset 16): pairs (i, i+4).
        float e4[4];
        #pragma unroll
        for (int i = 0; i < 4; i++) {
            const float send = (lane & 16) ? d[i]     : d[i + 4];
            const float keep = (lane & 16) ? d[i + 4] : d[i];
            e4[i] = keep + __shfl_xor_sync(FULLMASK, send, 16);
        }
        // Step B (offset 8): pairs (i, i+2).
        float f2[2];
        #pragma unroll
        for (int i = 0; i < 2; i++) {
            const float send = (lane & 8) ? e4[i]     : e4[i + 2];
            const float keep = (lane & 8) ? e4[i + 2] : e4[i];
            f2[i] = keep + __shfl_xor_sync(FULLMASK, send, 8);
        }
        // Step C (offset 4): pair (0, 1).
        {
            const float send = (lane & 4) ? f2[0] : f2[1];
            const float keep = (lane & 4) ? f2[1] : f2[0];
            f2[0] = keep + __shfl_xor_sync(FULLMASK, send, 4);
        }
        // Steps D/E: finish within the 4-lane group.
        float g = f2[0];
        g += __shfl_xor_sync(FULLMASK, g, 2);
        g += __shfl_xor_sync(FULLMASK, g, 1);
        // Now lane group k = lane>>2 holds the complete dot for position j=k.

        if (canon && j < n) {
            const float x = ((codemask >> j) & 1u) ? g : -g;
            accL += __logf(1.0f + __expf(-x));   // -log(sigmoid(x))
        }
        if (lane == 0) accC += (float)n;
    }

    // Warp-level reduce of per-lane accumulators (once, after the loop).
    #pragma unroll
    for (int off = 16; off > 0; off >>= 1) {
        accL += __shfl_xor_sync(FULLMASK, accL, off);
        accC += __shfl_xor_sync(FULLMASK, accC, off);
    }

    __shared__ float2 swsum[8];
    if (lane == 0) swsum[warp] = make_float2(accL, accC);
    __syncthreads();

    __shared__ bool is_last;
    if (tid == 0) {
        float2 t = make_float2(0.0f, 0.0f);
        #pragma unroll
        for (int i = 0; i < 8; i++) { t.x += swsum[i].x; t.y += swsum[i].y; }
        g_hs_partial[blockIdx.x] = t;
        __threadfence();
        const unsigned prev = atomicAdd(&g_hs_ctr, 1u);
        is_last = (prev == (unsigned)(gridDim.x - 1));
    }
    __syncthreads();

    // Last CTA reduces the partials in fixed order and writes the scalar.
    if (is_last) {
        float ls = 0.0f, cs = 0.0f;
        #pragma unroll
        for (int i = 0; i < 4; i++) {
            const int k = tid + i * 256;
            if (k < HS_GRID) {
                const float2 v = __ldcg(&g_hs_partial[k]);
                ls += v.x;
                cs += v.y;
            }
        }
        #pragma unroll
        for (int off = 16; off > 0; off >>= 1) {
            ls += __shfl_xor_sync(FULLMASK, ls, off);
            cs += __shfl_xor_sync(FULLMASK, cs, off);
        }
        __shared__ float sl[8], sc[8];
        if (lane == 0) { sl[warp] = ls; sc[warp] = cs; }
        __syncthreads();
        if (tid == 0) {
            float tl = 0.0f, tc = 0.0f;
            #pragma unroll
            for (int i = 0; i < 8; i++) { tl += sl[i]; tc += sc[i]; }
            out[0] = (float)((double)tl / (double)tc);
            g_hs_ctr = 0;   // reset for next graph replay
        }
    }
}

// ---------------------------------------------------------------------------
// Inputs (metadata order): hidden_ f32[B,D], target i32[B] (unused),
// target_path i32[B,P], target_path_len i32[B], target_code i32[B,P],
// embed_table f32[V,D].  Output: f32 scalar.
// ---------------------------------------------------------------------------
extern "C" void kernel_launch(void* const* d_in, const int* in_sizes, int n_in,
                              void* d_out, int out_size) {
    const float* hidden      = (const float*)d_in[0];
    const int*   target_path = (const int*)  d_in[2];
    const int*   path_len    = (const int*)  d_in[3];
    const int*   target_code = (const int*)  d_in[4];
    const float* embed_table = (const float*)d_in[5];
    float*       out         = (float*)d_out;

    hs_fused_kernel<<<HS_GRID, 256>>>(hidden, target_path, path_len,
                                      target_code, embed_table, out);
}

// round 8
// speedup vs baseline: 2.2055x; 1.0025x over previous
#include <cuda_runtime.h>
#include <cuda_bf16.h>
#include <math.h>

#define HS_B     8192
#define HS_P     32
#define HS_D     128
#define HS_GRID  888                // 148 SMs x 6 CTAs
#define HS_ITEMS (HS_B * 4)         // (row, 8-pos chunk) work items
#define FULLMASK 0xffffffffu

// Per-CTA {loss_sum, count} partials + completion counter (zero-init).
__device__ float2       g_hs_partial[HS_GRID];
__device__ unsigned int g_hs_ctr;

// ---------------------------------------------------------------------------
// Balanced persistent kernel with a software-pipelined item loop: while item
// k's gathers + merge network run, item k+1's path_len / indices / codes are
// already in flight, removing the serial idx-chain from the critical path.
// Item = (b, c): positions [8c, 8c+8) of row b. Lanes 0..7 carry the item's
// 8 indices/codes. After the folding merge network, lane group k = lane>>2
// holds the complete dot for position k => 8-lane-parallel softplus.
// ---------------------------------------------------------------------------
__global__ __launch_bounds__(256, 6)
void hs_fused_kernel(const float* __restrict__ hidden,
                     const int*   __restrict__ target_path,
                     const int*   __restrict__ target_path_len,
                     const int*   __restrict__ target_code,
                     const float* __restrict__ embed_table,
                     float*       __restrict__ out) {
    const int tid  = threadIdx.x;
    const int warp = tid >> 5;
    const int lane = tid & 31;
    const int gw   = blockIdx.x * 8 + warp;
    const int GW   = gridDim.x * 8;

    const int  j     = lane >> 2;           // value index this lane finalizes
    const bool canon = (lane & 3) == 0;     // one canonical lane per value

    float accL = 0.0f;                      // per-lane loss accumulator
    float accC = 0.0f;                      // count accumulator (lane 0)

    // ---- pipeline prologue: load item 0's control data ----
    int b = 0, base = 0, L = 0, idx_l = 0, code_l = 0;
    if (gw < HS_ITEMS) {
        b    = gw >> 2;
        base = (gw & 3) * 8;
        L    = __ldg(&target_path_len[b]);
        if (lane < 8) {
            idx_l  = target_path[b * HS_P + base + lane];
            code_l = target_code[b * HS_P + base + lane];
        }
    }

    for (int item = gw; item < HS_ITEMS; item += GW) {
        // ---- issue next item's control loads (independent of this item) ----
        const int nitem = item + GW;
        int nb = 0, nbase = 0, nL = 0, nidx = 0, ncode = 0;
        if (nitem < HS_ITEMS) {
            nb    = nitem >> 2;
            nbase = (nitem & 3) * 8;
            nL    = __ldg(&target_path_len[nb]);
            if (lane < 8) {
                nidx  = target_path[nb * HS_P + nbase + lane];
                ncode = target_code[nb * HS_P + nbase + lane];
            }
        }

        // ---- current item's compute ----
        if (base < L) {
            const int n = min(8, L - base);
            const unsigned codemask =
                __ballot_sync(FULLMASK, (lane < 8) && (code_l != 0));

            // Hidden row: one float4 per lane (512 B, L2-resident).
            const float4 hv =
                reinterpret_cast<const float4*>(hidden + (size_t)b * HS_D)[lane];

            // Up to 8 independent embed-row gathers in flight.
            float d[8];
            #pragma unroll
            for (int i = 0; i < 8; i++) {
                const int node = __shfl_sync(FULLMASK, idx_l, i);
                d[i] = 0.0f;
                if (i < n) {
                    const float4 e = reinterpret_cast<const float4*>(
                        embed_table + (size_t)node * HS_D)[lane];
                    d[i] = fmaf(e.x, hv.x, fmaf(e.y, hv.y,
                                fmaf(e.z, hv.z, e.w * hv.w)));
                }
            }

            // Folding merge network: 8 values -> 1 per 4-lane group.
            float e4[4];
            #pragma unroll
            for (int i = 0; i < 4; i++) {
                const float send = (lane & 16) ? d[i]     : d[i + 4];
                const float keep = (lane & 16) ? d[i + 4] : d[i];
                e4[i] = keep + __shfl_xor_sync(FULLMASK, send, 16);
            }
            float f2[2];
            #pragma unroll
            for (int i = 0; i < 2; i++) {
                const float send = (lane & 8) ? e4[i]     : e4[i + 2];
                const float keep = (lane & 8) ? e4[i + 2] : e4[i];
                f2[i] = keep + __shfl_xor_sync(FULLMASK, send, 8);
            }
            {
                const float send = (lane & 4) ? f2[0] : f2[1];
                const float keep = (lane & 4) ? f2[1] : f2[0];
                f2[0] = keep + __shfl_xor_sync(FULLMASK, send, 4);
            }
            float g = f2[0];
            g += __shfl_xor_sync(FULLMASK, g, 2);
            g += __shfl_xor_sync(FULLMASK, g, 1);
            // Lane group k = lane>>2 holds the complete dot for position k.

            if (canon && j < n) {
                const float x = ((codemask >> j) & 1u) ? g : -g;
                accL += __logf(1.0f + __expf(-x));   // -log(sigmoid(x))
            }
            if (lane == 0) accC += (float)n;
        }

        // ---- rotate pipeline registers ----
        b = nb; base = nbase; L = nL; idx_l = nidx; code_l = ncode;
    }

    // Warp-level reduce of per-lane accumulators (once, after the loop).
    #pragma unroll
    for (int off = 16; off > 0; off >>= 1) {
        accL += __shfl_xor_sync(FULLMASK, accL, off);
        accC += __shfl_xor_sync(FULLMASK, accC, off);
    }

    __shared__ float2 swsum[8];
    if (lane == 0) swsum[warp] = make_float2(accL, accC);
    __syncthreads();

    __shared__ bool is_last;
    if (tid == 0) {
        float2 t = make_float2(0.0f, 0.0f);
        #pragma unroll
        for (int i = 0; i < 8; i++) { t.x += swsum[i].x; t.y += swsum[i].y; }
        g_hs_partial[blockIdx.x] = t;
        __threadfence();
        const unsigned prev = atomicAdd(&g_hs_ctr, 1u);
        is_last = (prev == (unsigned)(gridDim.x - 1));
    }
    __syncthreads();

    // Last CTA reduces the partials in fixed order and writes the scalar.
    if (is_last) {
        float ls = 0.0f, cs = 0.0f;
        #pragma unroll
        for (int i = 0; i < 4; i++) {
            const int k = tid + i * 256;
            if (k < HS_GRID) {
                const float2 v = __ldcg(&g_hs_partial[k]);
                ls += v.x;
                cs += v.y;
            }
        }
        #pragma unroll
        for (int off = 16; off > 0; off >>= 1) {
            ls += __shfl_xor_sync(FULLMASK, ls, off);
            cs += __shfl_xor_sync(FULLMASK, cs, off);
        }
        __shared__ float sl[8], sc[8];
        if (lane == 0) { sl[warp] = ls; sc[warp] = cs; }
        __syncthreads();
        if (tid == 0) {
            float tl = 0.0f, tc = 0.0f;
            #pragma unroll
            for (int i = 0; i < 8; i++) { tl += sl[i]; tc += sc[i]; }
            out[0] = (float)((double)tl / (double)tc);
            g_hs_ctr = 0;   // reset for next graph replay
        }
    }
}

// ---------------------------------------------------------------------------
// Inputs (metadata order): hidden_ f32[B,D], target i32[B] (unused),
// target_path i32[B,P], target_path_len i32[B], target_code i32[B,P],
// embed_table f32[V,D].  Output: f32 scalar.
// ---------------------------------------------------------------------------
extern "C" void kernel_launch(void* const* d_in, const int* in_sizes, int n_in,
                              void* d_out, int out_size) {
    const float* hidden      = (const float*)d_in[0];
    const int*   target_path = (const int*)  d_in[2];
    const int*   path_len    = (const int*)  d_in[3];
    const int*   target_code = (const int*)  d_in[4];
    const float* embed_table = (const float*)d_in[5];
    float*       out         = (float*)d_out;

    hs_fused_kernel<<<HS_GRID, 256>>>(hidden, target_path, path_len,
                                      target_code, embed_table, out);
}